// round 1
// baseline (speedup 1.0000x reference)
#include <cuda_runtime.h>
#include <math.h>

#define NLAYER 2
#define DMODEL 768
#define VOCAB  32000
#define DSTATE 16
#define DINNER 1536
#define DTRANK 48
#define BB 2
#define LL 1024
#define BL (BB*LL)
#define XDW 80   // DT_RANK + 2*D_STATE

// ---------------- scratch (device globals; no allocation allowed) ----------
__device__ float g_X   [BL*DMODEL];          // residual stream
__device__ float g_XN  [BL*DMODEL];          // rmsnorm output
__device__ float g_XZ  [BL*2*DINNER];        // in_proj output
__device__ float g_U   [BL*DINNER];          // silu(conv(xs))
__device__ float g_XDBL[BL*XDW];             // x_proj output (delta|B|C)
__device__ float g_DT  [BL*DINNER];          // softplus(dt)
__device__ float g_Y   [BL*DINNER];          // scan output * silu(res)
__device__ float g_ES  [(size_t)BL*DINNER*DSTATE];  // exp(suffix cumsum dA), 201MB

// ---------------- embedding gather -----------------------------------------
__global__ void embed_kernel(const int* __restrict__ ids,
                             const float* __restrict__ emb,
                             float* __restrict__ X) {
    int r = blockIdx.x;
    int id = ids[r];
    const float* src = emb + (size_t)id * DMODEL;
    float* dst = X + (size_t)r * DMODEL;
    for (int d = threadIdx.x; d < DMODEL; d += blockDim.x) dst[d] = src[d];
}

// ---------------- rmsnorm ---------------------------------------------------
__global__ void rmsnorm_kernel(const float* __restrict__ X,
                               const float* __restrict__ w,
                               float* __restrict__ O) {
    int r = blockIdx.x;
    const float* x = X + (size_t)r * DMODEL;
    float s = 0.f;
    for (int d = threadIdx.x; d < DMODEL; d += 256) { float v = x[d]; s += v * v; }
    __shared__ float sh[8];
    int lane = threadIdx.x & 31, wrp = threadIdx.x >> 5;
    #pragma unroll
    for (int o = 16; o > 0; o >>= 1) s += __shfl_xor_sync(0xffffffffu, s, o);
    if (lane == 0) sh[wrp] = s;
    __syncthreads();
    if (threadIdx.x == 0) {
        float t = 0.f;
        #pragma unroll
        for (int i = 0; i < 8; i++) t += sh[i];
        sh[0] = rsqrtf(t / (float)DMODEL + 1e-5f);
    }
    __syncthreads();
    float inv = sh[0];
    float* o = O + (size_t)r * DMODEL;
    for (int d = threadIdx.x; d < DMODEL; d += 256) o[d] = x[d] * inv * w[d];
}

// ---------------- generic SGEMM: C[M,N] = A[M,K] * B[N,K]^T -----------------
// mode 0: C = acc ; mode 1: C += acc ; mode 2: C = softplus(acc + bias[col])
__global__ __launch_bounds__(256, 2) void gemm_nt_kernel(
    const float* __restrict__ A, int lda,
    const float* __restrict__ B, int ldb,
    float* __restrict__ C, int ldc,
    int M, int N, int K, int mode, const float* __restrict__ bias)
{
    __shared__ float As[8][128];
    __shared__ float Bs[8][128];
    const int tid  = threadIdx.x;
    const int brow = blockIdx.y * 128;
    const int bcol = blockIdx.x * 128;
    const int tx = tid & 15;
    const int ty = tid >> 4;
    const int ldRow = tid >> 1;
    const int ldK   = (tid & 1) * 4;
    const float* Ap = A + (size_t)(brow + ldRow) * lda + ldK;
    const bool  bvd = (bcol + ldRow) < N;
    const float* Bp = B + (size_t)(bcol + ldRow) * ldb + ldK;

    float acc[8][8];
    #pragma unroll
    for (int i = 0; i < 8; i++)
        #pragma unroll
        for (int j = 0; j < 8; j++) acc[i][j] = 0.f;

    for (int k0 = 0; k0 < K; k0 += 8) {
        float4 a4 = *(const float4*)(Ap + k0);
        float4 b4 = bvd ? *(const float4*)(Bp + k0) : make_float4(0.f, 0.f, 0.f, 0.f);
        __syncthreads();
        As[ldK + 0][ldRow] = a4.x; As[ldK + 1][ldRow] = a4.y;
        As[ldK + 2][ldRow] = a4.z; As[ldK + 3][ldRow] = a4.w;
        Bs[ldK + 0][ldRow] = b4.x; Bs[ldK + 1][ldRow] = b4.y;
        Bs[ldK + 2][ldRow] = b4.z; Bs[ldK + 3][ldRow] = b4.w;
        __syncthreads();
        #pragma unroll
        for (int kk = 0; kk < 8; kk++) {
            float4 a0 = *(const float4*)&As[kk][ty * 8];
            float4 a1 = *(const float4*)&As[kk][ty * 8 + 4];
            float4 b0 = *(const float4*)&Bs[kk][tx * 8];
            float4 b1 = *(const float4*)&Bs[kk][tx * 8 + 4];
            float ar[8] = {a0.x, a0.y, a0.z, a0.w, a1.x, a1.y, a1.z, a1.w};
            float br[8] = {b0.x, b0.y, b0.z, b0.w, b1.x, b1.y, b1.z, b1.w};
            #pragma unroll
            for (int i = 0; i < 8; i++)
                #pragma unroll
                for (int j = 0; j < 8; j++)
                    acc[i][j] += ar[i] * br[j];
        }
    }

    #pragma unroll
    for (int i = 0; i < 8; i++) {
        int row = brow + ty * 8 + i;
        if (row >= M) continue;
        #pragma unroll
        for (int j = 0; j < 8; j++) {
            int col = bcol + tx * 8 + j;
            if (col < N) {
                size_t idx = (size_t)row * ldc + col;
                float v = acc[i][j];
                if (mode == 1) v += C[idx];
                else if (mode == 2) {
                    v += bias[col];
                    v = fmaxf(v, 0.f) + log1pf(expf(-fabsf(v)));  // stable softplus
                }
                C[idx] = v;
            }
        }
    }
}

// ---------------- depthwise causal conv (k=4) + silu ------------------------
__global__ void conv_silu_kernel(const float* __restrict__ XZ,
                                 const float* __restrict__ cw,
                                 const float* __restrict__ cb,
                                 float* __restrict__ U) {
    int d = blockIdx.x * blockDim.x + threadIdx.x;
    int r = blockIdx.y;
    if (d >= DINNER) return;
    int l = r & (LL - 1);
    float w0 = cw[d * 4 + 0], w1 = cw[d * 4 + 1], w2 = cw[d * 4 + 2], w3 = cw[d * 4 + 3];
    const float* Xp = XZ + (size_t)r * (2 * DINNER) + d;
    float acc = cb[d] + w3 * Xp[0];
    if (l >= 1) acc += w2 * Xp[-(2 * DINNER)];
    if (l >= 2) acc += w1 * Xp[-2 * (2 * DINNER)];
    if (l >= 3) acc += w0 * Xp[-3 * (2 * DINNER)];
    U[(size_t)r * DINNER + d] = acc / (1.f + expf(-acc));  // silu
}

// ---------------- selective scan (replicates reference's exp-of-suffix-cumsum
// formulation, incl. its fp32 underflow + 1e-12 denominator behavior) --------
__global__ void scan_kernel(const float* __restrict__ DT, const float* __restrict__ U,
                            const float* __restrict__ XD, const float* __restrict__ Alog,
                            const float* __restrict__ Dp, const float* __restrict__ XZ,
                            float* __restrict__ Y, float* __restrict__ ES)
{
    int b  = blockIdx.y;
    int n  = threadIdx.x & 15;
    int dl = threadIdx.x >> 4;
    int d  = blockIdx.x * 16 + dl;
    float A = -expf(Alog[d * DSTATE + n]);

    // backward pass: ES[l] = exp(sum_{j>l} dA[j])
    float S = 0.f;
    for (int l = LL - 1; l >= 0; --l) {
        int r = b * LL + l;
        ES[(size_t)r * (DINNER * DSTATE) + d * DSTATE + n] = expf(S);
        S += DT[(size_t)r * DINNER + d] * A;
    }

    // forward pass: x[l] = cumsum(dB_u * ES) / (ES + 1e-12); y = x . C + u*D
    float num = 0.f;
    float Dv = Dp[d];
    for (int l = 0; l < LL; ++l) {
        int r = b * LL + l;
        float dt = DT[(size_t)r * DINNER + d];
        float u  = U [(size_t)r * DINNER + d];
        float es = ES[(size_t)r * (DINNER * DSTATE) + d * DSTATE + n];
        float Bm = XD[(size_t)r * XDW + DTRANK + n];
        float Cm = XD[(size_t)r * XDW + DTRANK + DSTATE + n];
        num += dt * u * Bm * es;
        float part = (num / (es + 1e-12f)) * Cm;
        part += __shfl_xor_sync(0xffffffffu, part, 8);
        part += __shfl_xor_sync(0xffffffffu, part, 4);
        part += __shfl_xor_sync(0xffffffffu, part, 2);
        part += __shfl_xor_sync(0xffffffffu, part, 1);
        if (n == 0) {
            float y   = part + u * Dv;
            float res = XZ[(size_t)r * (2 * DINNER) + DINNER + d];
            Y[(size_t)r * DINNER + d] = y * (res / (1.f + expf(-res)));  // * silu(res)
        }
    }
}

// ---------------- driver ----------------------------------------------------
extern "C" void kernel_launch(void* const* d_in, const int* in_sizes, int n_in,
                              void* d_out, int out_size) {
    const int*   ids       = (const int*)  d_in[0];
    const float* emb       = (const float*)d_in[1];
    const float* W_in      = (const float*)d_in[2];
    const float* conv_w    = (const float*)d_in[3];
    const float* conv_b    = (const float*)d_in[4];
    const float* x_proj_w  = (const float*)d_in[5];
    const float* dt_proj_w = (const float*)d_in[6];
    const float* dt_proj_b = (const float*)d_in[7];
    const float* A_log     = (const float*)d_in[8];
    const float* D_param   = (const float*)d_in[9];
    const float* W_out     = (const float*)d_in[10];
    const float* norm_w    = (const float*)d_in[11];
    const float* norm_f_w  = (const float*)d_in[12];
    float* out = (float*)d_out;

    float *pX, *pXN, *pXZ, *pU, *pXDBL, *pDT, *pY, *pES;
    cudaGetSymbolAddress((void**)&pX,    g_X);
    cudaGetSymbolAddress((void**)&pXN,   g_XN);
    cudaGetSymbolAddress((void**)&pXZ,   g_XZ);
    cudaGetSymbolAddress((void**)&pU,    g_U);
    cudaGetSymbolAddress((void**)&pXDBL, g_XDBL);
    cudaGetSymbolAddress((void**)&pDT,   g_DT);
    cudaGetSymbolAddress((void**)&pY,    g_Y);
    cudaGetSymbolAddress((void**)&pES,   g_ES);

    embed_kernel<<<BL, 256>>>(ids, emb, pX);

    for (int i = 0; i < NLAYER; i++) {
        rmsnorm_kernel<<<BL, 256>>>(pX, norm_w + (size_t)i * DMODEL, pXN);

        // xz = xn @ W_in^T : (2048,768) x (3072,768)^T
        gemm_nt_kernel<<<dim3(2 * DINNER / 128, BL / 128), 256>>>(
            pXN, DMODEL, W_in + (size_t)i * 2 * DINNER * DMODEL, DMODEL,
            pXZ, 2 * DINNER, BL, 2 * DINNER, DMODEL, 0, nullptr);

        // u = silu(depthwise_conv(xs) + b)
        conv_silu_kernel<<<dim3(DINNER / 256, BL), 256>>>(
            pXZ, conv_w + (size_t)i * DINNER * 4, conv_b + (size_t)i * DINNER, pU);

        // x_dbl = u @ x_proj_w^T : (2048,1536) x (80,1536)^T
        gemm_nt_kernel<<<dim3(1, BL / 128), 256>>>(
            pU, DINNER, x_proj_w + (size_t)i * XDW * DINNER, DINNER,
            pXDBL, XDW, BL, XDW, DINNER, 0, nullptr);

        // dt = softplus(x_dbl[:, :48] @ dt_proj_w^T + b) : (2048,48) x (1536,48)^T
        gemm_nt_kernel<<<dim3(DINNER / 128, BL / 128), 256>>>(
            pXDBL, XDW, dt_proj_w + (size_t)i * DINNER * DTRANK, DTRANK,
            pDT, DINNER, BL, DINNER, DTRANK, 2, dt_proj_b + (size_t)i * DINNER);

        // selective scan + gating
        scan_kernel<<<dim3(DINNER / 16, BB), 256>>>(
            pDT, pU, pXDBL, A_log + (size_t)i * DINNER * DSTATE,
            D_param + (size_t)i * DINNER, pXZ, pY, pES);

        // x += y @ W_out^T : (2048,1536) x (768,1536)^T, accumulate residual
        gemm_nt_kernel<<<dim3(DMODEL / 128, BL / 128), 256>>>(
            pY, DINNER, W_out + (size_t)i * DMODEL * DINNER, DINNER,
            pX, DMODEL, BL, DMODEL, DINNER, 1, nullptr);
    }

    rmsnorm_kernel<<<BL, 256>>>(pX, norm_f_w, pXN);

    // logits = xn @ emb^T : (2048,768) x (32000,768)^T
    gemm_nt_kernel<<<dim3(VOCAB / 128, BL / 128), 256>>>(
        pXN, DMODEL, emb, DMODEL, out, VOCAB, BL, VOCAB, DMODEL, 0, nullptr);
}

// round 2
// speedup vs baseline: 2.0582x; 2.0582x over previous
#include <cuda_runtime.h>
#include <math.h>
#include <stdint.h>

#define NLAYER 2
#define DMODEL 768
#define VOCAB  32000
#define DSTATE 16
#define DINNER 1536
#define DTRANK 48
#define BB 2
#define LL 1024
#define BL (BB*LL)
#define XDW 80   // DT_RANK + 2*D_STATE
#define CHK 128  // scan checkpoint interval
#define NCHK (LL/CHK)

// ---------------- scratch (device globals; no allocation allowed) ----------
__device__ float g_X   [BL*DMODEL];          // residual stream
__device__ float g_XN  [BL*DMODEL];          // rmsnorm output
__device__ float g_XZ  [BL*2*DINNER];        // in_proj output
__device__ float g_U   [BL*DINNER];          // silu(conv(xs))
__device__ float g_XDBL[BL*XDW];             // x_proj output (delta|B|C)
__device__ float g_DT  [BL*DINNER];          // softplus(dt)
__device__ float g_Y   [BL*DINNER];          // scan output * silu(res)
__device__ float g_SC  [BB*DINNER*DSTATE*NCHK]; // scan suffix-sum checkpoints

// ---------------- embedding gather -----------------------------------------
__global__ void embed_kernel(const int* __restrict__ ids,
                             const float* __restrict__ emb,
                             float* __restrict__ X) {
    int r = blockIdx.x;
    int id = ids[r];
    const float* src = emb + (size_t)id * DMODEL;
    float* dst = X + (size_t)r * DMODEL;
    for (int d = threadIdx.x; d < DMODEL; d += blockDim.x) dst[d] = src[d];
}

// ---------------- rmsnorm ---------------------------------------------------
__global__ void rmsnorm_kernel(const float* __restrict__ X,
                               const float* __restrict__ w,
                               float* __restrict__ O) {
    int r = blockIdx.x;
    const float* x = X + (size_t)r * DMODEL;
    float s = 0.f;
    for (int d = threadIdx.x; d < DMODEL; d += 256) { float v = x[d]; s += v * v; }
    __shared__ float sh[8];
    int lane = threadIdx.x & 31, wrp = threadIdx.x >> 5;
    #pragma unroll
    for (int o = 16; o > 0; o >>= 1) s += __shfl_xor_sync(0xffffffffu, s, o);
    if (lane == 0) sh[wrp] = s;
    __syncthreads();
    if (threadIdx.x == 0) {
        float t = 0.f;
        #pragma unroll
        for (int i = 0; i < 8; i++) t += sh[i];
        sh[0] = rsqrtf(t / (float)DMODEL + 1e-5f);
    }
    __syncthreads();
    float inv = sh[0];
    float* o = O + (size_t)r * DMODEL;
    for (int d = threadIdx.x; d < DMODEL; d += 256) o[d] = x[d] * inv * w[d];
}

// ---------------- TF32 tensor-core GEMM: C[M,N] = A[M,K] * B[N,K]^T ---------
// mode 0: C = acc ; mode 1: C += acc ; mode 2: C = softplus(acc + bias[col])
// M must be a multiple of 128; K a multiple of 16. N arbitrary (guarded).
__device__ __forceinline__ uint32_t f2tf(float f) {
    uint32_t r;
    asm("cvt.rna.tf32.f32 %0, %1;" : "=r"(r) : "f"(f));
    return r;
}

#define KSTR 20  // smem k-stride (16 + pad 4): 20*g mod 32 hits all banks

__global__ __launch_bounds__(256) void gemm_tf32_kernel(
    const float* __restrict__ A, int lda,
    const float* __restrict__ B, int ldb,
    float* __restrict__ C, int ldc,
    int M, int N, int K, int mode, const float* __restrict__ bias)
{
    __shared__ uint32_t As[128 * KSTR];
    __shared__ uint32_t Bs[128 * KSTR];

    const int tid  = threadIdx.x;
    const int warp = tid >> 5;
    const int lane = tid & 31;
    const int g = lane >> 2;        // 0..7
    const int t = lane & 3;         // 0..3
    const int wm = (warp >> 2) * 64;   // 0 / 64
    const int wn = (warp & 3) * 32;    // 0,32,64,96
    const int brow = blockIdx.y * 128;
    const int bcol = blockIdx.x * 128;

    // global-load mapping: idx = tid + i*256 ; row = idx>>2 ; k4 = (idx&3)*4
    const int gr0 = tid >> 2;            // row for i=0
    const int gr1 = (tid + 256) >> 2;    // row for i=1
    const int gk  = (tid & 3) * 4;       // same k4 for both (tid&3 invariant +256)

    float c[4][4][4];
    #pragma unroll
    for (int mi = 0; mi < 4; mi++)
        #pragma unroll
        for (int ni = 0; ni < 4; ni++)
            #pragma unroll
            for (int q = 0; q < 4; q++) c[mi][ni][q] = 0.f;

    const int nk = K / 16;
    float4 aR0, aR1, bR0, bR1;
    const bool bv0 = (bcol + gr0) < N;
    const bool bv1 = (bcol + gr1) < N;

    // prefetch k-tile 0
    aR0 = *(const float4*)&A[(size_t)(brow + gr0) * lda + gk];
    aR1 = *(const float4*)&A[(size_t)(brow + gr1) * lda + gk];
    bR0 = bv0 ? *(const float4*)&B[(size_t)(bcol + gr0) * ldb + gk] : make_float4(0,0,0,0);
    bR1 = bv1 ? *(const float4*)&B[(size_t)(bcol + gr1) * ldb + gk] : make_float4(0,0,0,0);

    for (int kt = 0; kt < nk; kt++) {
        __syncthreads();
        As[gr0 * KSTR + gk + 0] = f2tf(aR0.x); As[gr0 * KSTR + gk + 1] = f2tf(aR0.y);
        As[gr0 * KSTR + gk + 2] = f2tf(aR0.z); As[gr0 * KSTR + gk + 3] = f2tf(aR0.w);
        As[gr1 * KSTR + gk + 0] = f2tf(aR1.x); As[gr1 * KSTR + gk + 1] = f2tf(aR1.y);
        As[gr1 * KSTR + gk + 2] = f2tf(aR1.z); As[gr1 * KSTR + gk + 3] = f2tf(aR1.w);
        Bs[gr0 * KSTR + gk + 0] = f2tf(bR0.x); Bs[gr0 * KSTR + gk + 1] = f2tf(bR0.y);
        Bs[gr0 * KSTR + gk + 2] = f2tf(bR0.z); Bs[gr0 * KSTR + gk + 3] = f2tf(bR0.w);
        Bs[gr1 * KSTR + gk + 0] = f2tf(bR1.x); Bs[gr1 * KSTR + gk + 1] = f2tf(bR1.y);
        Bs[gr1 * KSTR + gk + 2] = f2tf(bR1.z); Bs[gr1 * KSTR + gk + 3] = f2tf(bR1.w);
        __syncthreads();

        if (kt + 1 < nk) {
            int k0 = (kt + 1) * 16;
            aR0 = *(const float4*)&A[(size_t)(brow + gr0) * lda + k0 + gk];
            aR1 = *(const float4*)&A[(size_t)(brow + gr1) * lda + k0 + gk];
            bR0 = bv0 ? *(const float4*)&B[(size_t)(bcol + gr0) * ldb + k0 + gk] : make_float4(0,0,0,0);
            bR1 = bv1 ? *(const float4*)&B[(size_t)(bcol + gr1) * ldb + k0 + gk] : make_float4(0,0,0,0);
        }

        #pragma unroll
        for (int ks = 0; ks < 16; ks += 8) {
            uint32_t af[4][4], bf[4][2];
            #pragma unroll
            for (int mi = 0; mi < 4; mi++) {
                int mr = wm + mi * 16;
                af[mi][0] = As[(mr + g    ) * KSTR + ks + t    ];
                af[mi][1] = As[(mr + g + 8) * KSTR + ks + t    ];
                af[mi][2] = As[(mr + g    ) * KSTR + ks + t + 4];
                af[mi][3] = As[(mr + g + 8) * KSTR + ks + t + 4];
            }
            #pragma unroll
            for (int ni = 0; ni < 4; ni++) {
                int nr = wn + ni * 8;
                bf[ni][0] = Bs[(nr + g) * KSTR + ks + t    ];
                bf[ni][1] = Bs[(nr + g) * KSTR + ks + t + 4];
            }
            #pragma unroll
            for (int mi = 0; mi < 4; mi++)
                #pragma unroll
                for (int ni = 0; ni < 4; ni++) {
                    asm volatile(
                        "mma.sync.aligned.m16n8k8.row.col.f32.tf32.tf32.f32 "
                        "{%0,%1,%2,%3}, {%4,%5,%6,%7}, {%8,%9}, {%0,%1,%2,%3};\n"
                        : "+f"(c[mi][ni][0]), "+f"(c[mi][ni][1]),
                          "+f"(c[mi][ni][2]), "+f"(c[mi][ni][3])
                        : "r"(af[mi][0]), "r"(af[mi][1]), "r"(af[mi][2]), "r"(af[mi][3]),
                          "r"(bf[ni][0]), "r"(bf[ni][1]));
                }
        }
    }

    // epilogue
    #pragma unroll
    for (int mi = 0; mi < 4; mi++) {
        int r0 = brow + wm + mi * 16 + g;
        #pragma unroll
        for (int ni = 0; ni < 4; ni++) {
            int col = bcol + wn + ni * 8 + 2 * t;
            #pragma unroll
            for (int q = 0; q < 4; q++) {
                int rr = r0 + (q >> 1) * 8;
                int cc = col + (q & 1);
                if (cc < N) {
                    size_t idx = (size_t)rr * ldc + cc;
                    float v = c[mi][ni][q];
                    if (mode == 1) v += C[idx];
                    else if (mode == 2) {
                        v += bias[cc];
                        v = fmaxf(v, 0.f) + log1pf(expf(-fabsf(v)));
                    }
                    C[idx] = v;
                }
            }
        }
    }
}

// ---------------- depthwise causal conv (k=4) + silu ------------------------
__global__ void conv_silu_kernel(const float* __restrict__ XZ,
                                 const float* __restrict__ cw,
                                 const float* __restrict__ cb,
                                 float* __restrict__ U) {
    int d = blockIdx.x * blockDim.x + threadIdx.x;
    int r = blockIdx.y;
    if (d >= DINNER) return;
    int l = r & (LL - 1);
    float w0 = cw[d * 4 + 0], w1 = cw[d * 4 + 1], w2 = cw[d * 4 + 2], w3 = cw[d * 4 + 3];
    const float* Xp = XZ + (size_t)r * (2 * DINNER) + d;
    float acc = cb[d] + w3 * Xp[0];
    if (l >= 1) acc += w2 * Xp[-(2 * DINNER)];
    if (l >= 2) acc += w1 * Xp[-2 * (2 * DINNER)];
    if (l >= 3) acc += w0 * Xp[-3 * (2 * DINNER)];
    U[(size_t)r * DINNER + d] = acc / (1.f + expf(-acc));  // silu
}

// ---------------- selective scan (replicates reference's exp-of-suffix-cumsum
// formulation incl. fp32 underflow + 1e-12 denominator). Backward pass stores
// only NCHK suffix-sum checkpoints per (d,n); forward recomputes S by
// subtraction. -------------------------------------------------------------
__global__ void scan_kernel(const float* __restrict__ DT, const float* __restrict__ U,
                            const float* __restrict__ XD, const float* __restrict__ Alog,
                            const float* __restrict__ Dp, const float* __restrict__ XZ,
                            float* __restrict__ Y, float* __restrict__ SC)
{
    int b  = blockIdx.y;
    int n  = threadIdx.x & 15;
    int dl = threadIdx.x >> 4;
    int d  = blockIdx.x * 16 + dl;
    float A = -expf(Alog[d * DSTATE + n]);
    size_t cbase = ((size_t)b * DINNER * DSTATE + (size_t)d * DSTATE + n) * NCHK;

    // backward pass: checkpoint S_l = sum_{j>l} dA_j at l % CHK == 0
    float S = 0.f;
    for (int l = LL - 1; l >= 0; --l) {
        int r = b * LL + l;
        if ((l & (CHK - 1)) == 0) SC[cbase + (l >> 7)] = S;
        S += DT[(size_t)r * DINNER + d] * A;
    }

    // forward pass
    float num = 0.f;
    float Dv = Dp[d];
    S = 0.f;
    for (int l = 0; l < LL; ++l) {
        int r = b * LL + l;
        float dt = DT[(size_t)r * DINNER + d];
        if ((l & (CHK - 1)) == 0) S = SC[cbase + (l >> 7)];
        else S -= dt * A;
        float es = expf(S);
        float u  = U[(size_t)r * DINNER + d];
        float Bm = XD[(size_t)r * XDW + DTRANK + n];
        float Cm = XD[(size_t)r * XDW + DTRANK + DSTATE + n];
        num += dt * u * Bm * es;
        float part = (num / (es + 1e-12f)) * Cm;
        part += __shfl_xor_sync(0xffffffffu, part, 8);
        part += __shfl_xor_sync(0xffffffffu, part, 4);
        part += __shfl_xor_sync(0xffffffffu, part, 2);
        part += __shfl_xor_sync(0xffffffffu, part, 1);
        if (n == 0) {
            float y   = part + u * Dv;
            float res = XZ[(size_t)r * (2 * DINNER) + DINNER + d];
            Y[(size_t)r * DINNER + d] = y * (res / (1.f + expf(-res)));
        }
    }
}

// ---------------- driver ----------------------------------------------------
extern "C" void kernel_launch(void* const* d_in, const int* in_sizes, int n_in,
                              void* d_out, int out_size) {
    const int*   ids       = (const int*)  d_in[0];
    const float* emb       = (const float*)d_in[1];
    const float* W_in      = (const float*)d_in[2];
    const float* conv_w    = (const float*)d_in[3];
    const float* conv_b    = (const float*)d_in[4];
    const float* x_proj_w  = (const float*)d_in[5];
    const float* dt_proj_w = (const float*)d_in[6];
    const float* dt_proj_b = (const float*)d_in[7];
    const float* A_log     = (const float*)d_in[8];
    const float* D_param   = (const float*)d_in[9];
    const float* W_out     = (const float*)d_in[10];
    const float* norm_w    = (const float*)d_in[11];
    const float* norm_f_w  = (const float*)d_in[12];
    float* out = (float*)d_out;

    float *pX, *pXN, *pXZ, *pU, *pXDBL, *pDT, *pY, *pSC;
    cudaGetSymbolAddress((void**)&pX,    g_X);
    cudaGetSymbolAddress((void**)&pXN,   g_XN);
    cudaGetSymbolAddress((void**)&pXZ,   g_XZ);
    cudaGetSymbolAddress((void**)&pU,    g_U);
    cudaGetSymbolAddress((void**)&pXDBL, g_XDBL);
    cudaGetSymbolAddress((void**)&pDT,   g_DT);
    cudaGetSymbolAddress((void**)&pY,    g_Y);
    cudaGetSymbolAddress((void**)&pSC,   g_SC);

    embed_kernel<<<BL, 256>>>(ids, emb, pX);

    for (int i = 0; i < NLAYER; i++) {
        rmsnorm_kernel<<<BL, 256>>>(pX, norm_w + (size_t)i * DMODEL, pXN);

        // xz = xn @ W_in^T : (2048,768) x (3072,768)^T
        gemm_tf32_kernel<<<dim3(2 * DINNER / 128, BL / 128), 256>>>(
            pXN, DMODEL, W_in + (size_t)i * 2 * DINNER * DMODEL, DMODEL,
            pXZ, 2 * DINNER, BL, 2 * DINNER, DMODEL, 0, nullptr);

        // u = silu(depthwise_conv(xs) + b)
        conv_silu_kernel<<<dim3(DINNER / 256, BL), 256>>>(
            pXZ, conv_w + (size_t)i * DINNER * 4, conv_b + (size_t)i * DINNER, pU);

        // x_dbl = u @ x_proj_w^T : (2048,1536) x (80,1536)^T
        gemm_tf32_kernel<<<dim3(1, BL / 128), 256>>>(
            pU, DINNER, x_proj_w + (size_t)i * XDW * DINNER, DINNER,
            pXDBL, XDW, BL, XDW, DINNER, 0, nullptr);

        // dt = softplus(x_dbl[:, :48] @ dt_proj_w^T + b) : (2048,48) x (1536,48)^T
        gemm_tf32_kernel<<<dim3(DINNER / 128, BL / 128), 256>>>(
            pXDBL, XDW, dt_proj_w + (size_t)i * DINNER * DTRANK, DTRANK,
            pDT, DINNER, BL, DINNER, DTRANK, 2, dt_proj_b + (size_t)i * DINNER);

        // selective scan + gating
        scan_kernel<<<dim3(DINNER / 16, BB), 256>>>(
            pDT, pU, pXDBL, A_log + (size_t)i * DINNER * DSTATE,
            D_param + (size_t)i * DINNER, pXZ, pY, pSC);

        // x += y @ W_out^T : (2048,1536) x (768,1536)^T, accumulate residual
        gemm_tf32_kernel<<<dim3(DMODEL / 128, BL / 128), 256>>>(
            pY, DINNER, W_out + (size_t)i * DMODEL * DINNER, DINNER,
            pX, DMODEL, BL, DMODEL, DINNER, 1, nullptr);
    }

    rmsnorm_kernel<<<BL, 256>>>(pX, norm_f_w, pXN);

    // logits = xn @ emb^T : (2048,768) x (32000,768)^T
    gemm_tf32_kernel<<<dim3(VOCAB / 128, BL / 128), 256>>>(
        pXN, DMODEL, emb, DMODEL, out, VOCAB, BL, VOCAB, DMODEL, 0, nullptr);
}